// round 11
// baseline (speedup 1.0000x reference)
#include <cuda_runtime.h>
#include <cuda_bf16.h>

// BoundaryLoss: loss = sum_{b,c,d,h,w} Gx(q)^2 + 2*Gy(q)^2 (normalized),
// q = softmax(pred, axis=C) - onehot(target); 2-D sobel per depth slice
// (kd=1 kernels; padded depth edge slices contribute 0; sz == sx^T so the
// 3-channel sum collapses to Gx^2 + 2*Gy^2; conv padding=1 keeps H,W size).
// pred (2,4,96,160,160) f32, target (2,96,160,160) i32.
//
// R11: barrier-free / smem-free. Thread = one column over a 16-row strip.
// w-neighbors via warp shuffles (lanes 1..30 of each warp produce 30 cols),
// h-neighbors via per-thread rolling window. Pure fp32.

#define BB 2
#define CC 4
#define DD 96
#define HH 160
#define WW 160

#define STRIP 16
#define RT (HH / STRIP)             // 10
#define NBLK (BB * DD * RT)         // 1920 blocks
#define NTHREADS 192                // 6 warps x 30 cols = 180 >= 160
#define CHSTR (DD * HH * WW)

__device__ float g_partial[NBLK];
__device__ int   g_count = 0;

__global__ __launch_bounds__(NTHREADS)
void bl_main_kernel(const float* __restrict__ pred,
                    const int*   __restrict__ target,
                    float*       __restrict__ out)
{
    __shared__ float  warpsum[NTHREADS / 32];
    __shared__ double dwarpsum[NTHREADS / 32];
    __shared__ bool   is_last;

    const int blk   = blockIdx.x;
    const int st    = blk % RT;
    const int slice = blk / RT;
    const int b     = slice / DD;
    const int d     = slice - b * DD;
    const int h0    = st * STRIP;

    const float* p0 = pred + (size_t)(b * CC * DD + d) * (HH * WW);
    const int*   tg = target + (size_t)slice * (HH * WW);

    const int tid  = threadIdx.x;
    const int wi   = tid >> 5;
    const int lane = tid & 31;
    const int col  = wi * 30 + lane - 1;            // -1 .. 180
    const bool cval  = ((unsigned)col < (unsigned)WW);
    const bool accum = (lane >= 1) && (lane <= 30) && (col < WW);

    // double-buffered raw row staging
    float bx0[2], bx1[2], bx2[2], bx3[2];
    int   bt[2];
    bool  bok[2];

#define LOADRAW(BUF, R)                                                 \
    {                                                                   \
        const int  r_ = (R);                                            \
        const bool ok_ = cval && ((unsigned)r_ < (unsigned)HH);         \
        bok[BUF] = ok_;                                                 \
        if (ok_) {                                                      \
            const int off_ = r_ * WW + col;                             \
            bx0[BUF] = p0[off_];                                        \
            bx1[BUF] = p0[off_ + CHSTR];                                \
            bx2[BUF] = p0[off_ + 2 * CHSTR];                            \
            bx3[BUF] = p0[off_ + 3 * CHSTR];                            \
            bt[BUF]  = tg[off_];                                        \
        }                                                               \
    }

    // softmax -> q (4 classes), then u/v via shuffles (all lanes converged)
#define SMUV(BUF, U, V)                                                 \
    {                                                                   \
        float q0 = 0.f, q1 = 0.f, q2 = 0.f, q3 = 0.f;                   \
        if (bok[BUF]) {                                                 \
            const float e0 = __expf(bx0[BUF]), e1 = __expf(bx1[BUF]);   \
            const float e2 = __expf(bx2[BUF]), e3 = __expf(bx3[BUF]);   \
            const float r_ = __frcp_rn(e0 + e1 + e2 + e3);              \
            const int   t_ = bt[BUF];                                   \
            q0 = e0 * r_ - (t_ == 0); q1 = e1 * r_ - (t_ == 1);         \
            q2 = e2 * r_ - (t_ == 2); q3 = e3 * r_ - (t_ == 3);         \
        }                                                               \
        {                                                               \
            const float qm = __shfl_up_sync(0xffffffffu, q0, 1);        \
            const float qp = __shfl_down_sync(0xffffffffu, q0, 1);      \
            U[0] = (qm + qp) + 2.f * q0;  V[0] = qp - qm;               \
        }                                                               \
        {                                                               \
            const float qm = __shfl_up_sync(0xffffffffu, q1, 1);        \
            const float qp = __shfl_down_sync(0xffffffffu, q1, 1);      \
            U[1] = (qm + qp) + 2.f * q1;  V[1] = qp - qm;               \
        }                                                               \
        {                                                               \
            const float qm = __shfl_up_sync(0xffffffffu, q2, 1);        \
            const float qp = __shfl_down_sync(0xffffffffu, q2, 1);      \
            U[2] = (qm + qp) + 2.f * q2;  V[2] = qp - qm;               \
        }                                                               \
        {                                                               \
            const float qm = __shfl_up_sync(0xffffffffu, q3, 1);        \
            const float qp = __shfl_down_sync(0xffffffffu, q3, 1);      \
            U[3] = (qm + qp) + 2.f * q3;  V[3] = qp - qm;               \
        }                                                               \
    }

    float pu[4], pv[4], cu[4], cv[4];
    float ax = 0.f, ay = 0.f;

    // rows loaded: h0-1 -> b0, h0 -> b1, h0+1 -> b0, h0+2 -> b1, ...
    LOADRAW(0, h0 - 1);
    LOADRAW(1, h0);
    SMUV(0, pu, pv);            // row h0-1
    LOADRAW(0, h0 + 1);
    SMUV(1, cu, cv);            // row h0
    LOADRAW(1, h0 + 2);

#pragma unroll
    for (int k = 0; k < STRIP; k++) {
        float nu[4], nv[4];
        SMUV(k & 1, nu, nv);    // row h0+1+k
        if (k < STRIP - 2) LOADRAW(k & 1, h0 + 3 + k);
        if (accum) {
#pragma unroll
            for (int c = 0; c < 4; c++) {
                const float gx = (pv[c] + nv[c]) + 2.f * cv[c];
                const float gy = nu[c] - pu[c];
                ax += gx * gx;
                ay += gy * gy;
            }
        }
#pragma unroll
        for (int c = 0; c < 4; c++) {
            pu[c] = cu[c]; pv[c] = cv[c];
            cu[c] = nu[c]; cv[c] = nv[c];
        }
    }
#undef LOADRAW
#undef SMUV

    float acc = ax + 2.f * ay;

    // ---- block reduction -> per-block partial ----
#pragma unroll
    for (int o = 16; o > 0; o >>= 1)
        acc += __shfl_down_sync(0xffffffffu, acc, o);
    if (lane == 0) warpsum[wi] = acc;
    __syncthreads();

    if (tid == 0) {
        float sm = 0.f;
#pragma unroll
        for (int i = 0; i < NTHREADS / 32; i++) sm += warpsum[i];
        g_partial[blk] = sm;
        __threadfence();
        is_last = (atomicAdd(&g_count, 1) == NBLK - 1);
    }
    __syncthreads();

    // ---- last block: final reduction + output + counter reset ----
    if (is_last) {
        double sd = 0.0;
        for (int i = tid; i < NBLK; i += NTHREADS) sd += (double)g_partial[i];
#pragma unroll
        for (int o = 16; o > 0; o >>= 1)
            sd += __shfl_down_sync(0xffffffffu, sd, o);
        if (lane == 0) dwarpsum[wi] = sd;
        __syncthreads();
        if (tid == 0) {
            double tot = 0.0;
#pragma unroll
            for (int i = 0; i < NTHREADS / 32; i++) tot += dwarpsum[i];
            const double per_tensor = (double)BB * (DD + 2) * (HH + 2) * (WW + 2);
            out[0] = (float)(tot / per_tensor / (double)CC);
            g_count = 0;
        }
    }
}

extern "C" void kernel_launch(void* const* d_in, const int* in_sizes, int n_in,
                              void* d_out, int out_size)
{
    const float* pred   = (const float*)d_in[0];
    const int*   target = (const int*)d_in[1];
    float*       out    = (float*)d_out;

    bl_main_kernel<<<NBLK, NTHREADS>>>(pred, target, out);
}

// round 12
// speedup vs baseline: 1.6624x; 1.6624x over previous
#include <cuda_runtime.h>
#include <cuda_bf16.h>
#include <cuda_fp16.h>

// BoundaryLoss: loss = sum_{b,c,d,h,w} Gx(q)^2 + 2*Gy(q)^2 (normalized),
// q = softmax(pred, axis=C) - onehot(target); 2-D sobel per depth slice.
// pred (2,4,96,160,160) f32, target (2,96,160,160) i32.
// R12 = R6 tile body (fp16 q smem, half2 sobel) run as exactly one wave:
// 592 blocks x 3-4 contiguous tiles each (kills wave-quantization tail).

#define BB 2
#define CC 4
#define DD 96
#define HH 160
#define WW 160

#define TH 16                       // output rows per tile
#define HALO (TH + 2)               // 18
#define RTILES (HH / TH)            // 10
#define NTILE (BB * DD * RTILES)    // 1920
#define NPBLK 592                   // 148 SMs x 4 blocks, one wave
#define K4BLK 144                   // first 144 blocks take 4 tiles (rest 3)
#define NTHREADS 320
#define NWARP (NTHREADS / 32)
#define PITCHB 336                  // bytes/row: [4 guard][160 data][4 guard] halfs

#define CHSTR4 (DD * HH * WW / 4)

__device__ float g_partial[NPBLK];
__device__ int   g_count = 0;

__device__ __forceinline__ __half2 u2h(unsigned x) {
    return *reinterpret_cast<__half2*>(&x);
}
__device__ __forceinline__ unsigned h2u(__half2 x) {
    return *reinterpret_cast<unsigned*>(&x);
}

__global__ __launch_bounds__(NTHREADS, 4)
void bl_main_kernel(const float* __restrict__ pred,
                    const int*   __restrict__ target,
                    float*       __restrict__ out)
{
    __shared__ __align__(16) unsigned char qsm[CC * HALO * PITCHB];  // 24192 B
    __shared__ float warpsum[NWARP];
    __shared__ double dwarpsum[NWARP];
    __shared__ bool  is_last;

    const int tid = threadIdx.x;

    // ---- tile range for this block (contiguous) ----
    int t0, ntl;
    if (blockIdx.x < K4BLK) { t0 = blockIdx.x * 4;                   ntl = 4; }
    else                    { t0 = K4BLK * 4 + (blockIdx.x - K4BLK) * 3; ntl = 3; }

    // ---- guard halfs: zero [0..3] and [164..167] per (c,row); once ----
    if (tid < CC * HALO * 2) {
        const int c    = tid / (HALO * 2);
        const int rem  = tid - c * (HALO * 2);
        const int row  = rem >> 1;
        const int side = rem & 1;
        *(uint2*)(qsm + (c * HALO + row) * PITCHB + (side ? 328 : 0)) = make_uint2(0u, 0u);
    }

    // phase-2 mapping: (class c2, 4-col group g2, 8-row strip s2); 4*40*2=320
    const int c2   = tid / 80;
    const int rem2 = tid - c2 * 80;
    const int s2   = rem2 / 40;
    const int g2   = rem2 - s2 * 40;
    const int off2 = 8 * g2;
    const unsigned char* rbase = qsm + (c2 * HALO + s2 * 8) * PITCHB;

    float axs = 0.f, ays = 0.f;

    for (int t = t0; t < t0 + ntl; t++) {
        const int rt    = t % RTILES;
        const int slice = t / RTILES;
        const int b     = slice / DD;
        const int d     = slice - b * DD;
        const int h0    = rt * TH;

        const float* pred_bd = pred + (size_t)(b * CC * DD + d) * (HH * WW);
        const int*   tgt_bd  = target + (size_t)slice * (HH * WW);

        // ---- Phase 1: q = softmax - onehot (fp32 math, fp16 store) ----
        for (int p = tid; p < HALO * (WW / 4); p += NTHREADS) {
            const int j  = p / (WW / 4);
            const int vc = p - j * (WW / 4);
            const int h  = h0 + j - 1;
            uint2 s0 = make_uint2(0u, 0u), s1 = s0, s2v = s0, s3 = s0;
            if ((unsigned)h < (unsigned)HH) {
                const float4* pr = (const float4*)(pred_bd + h * WW) + vc;
                const float4 x0 = pr[0];
                const float4 x1 = pr[CHSTR4];
                const float4 x2 = pr[2 * CHSTR4];
                const float4 x3 = pr[3 * CHSTR4];
                const int4   tt = ((const int4*)(tgt_bd + h * WW))[vc];
                float4 q0, q1, q2, q3;
                {
                    float e0 = __expf(x0.x), e1 = __expf(x1.x), e2 = __expf(x2.x), e3 = __expf(x3.x);
                    float r = __frcp_rn(e0 + e1 + e2 + e3);
                    q0.x = e0 * r - (tt.x == 0); q1.x = e1 * r - (tt.x == 1);
                    q2.x = e2 * r - (tt.x == 2); q3.x = e3 * r - (tt.x == 3);
                }
                {
                    float e0 = __expf(x0.y), e1 = __expf(x1.y), e2 = __expf(x2.y), e3 = __expf(x3.y);
                    float r = __frcp_rn(e0 + e1 + e2 + e3);
                    q0.y = e0 * r - (tt.y == 0); q1.y = e1 * r - (tt.y == 1);
                    q2.y = e2 * r - (tt.y == 2); q3.y = e3 * r - (tt.y == 3);
                }
                {
                    float e0 = __expf(x0.z), e1 = __expf(x1.z), e2 = __expf(x2.z), e3 = __expf(x3.z);
                    float r = __frcp_rn(e0 + e1 + e2 + e3);
                    q0.z = e0 * r - (tt.z == 0); q1.z = e1 * r - (tt.z == 1);
                    q2.z = e2 * r - (tt.z == 2); q3.z = e3 * r - (tt.z == 3);
                }
                {
                    float e0 = __expf(x0.w), e1 = __expf(x1.w), e2 = __expf(x2.w), e3 = __expf(x3.w);
                    float r = __frcp_rn(e0 + e1 + e2 + e3);
                    q0.w = e0 * r - (tt.w == 0); q1.w = e1 * r - (tt.w == 1);
                    q2.w = e2 * r - (tt.w == 2); q3.w = e3 * r - (tt.w == 3);
                }
                s0 = make_uint2(h2u(__floats2half2_rn(q0.x, q0.y)), h2u(__floats2half2_rn(q0.z, q0.w)));
                s1 = make_uint2(h2u(__floats2half2_rn(q1.x, q1.y)), h2u(__floats2half2_rn(q1.z, q1.w)));
                s2v = make_uint2(h2u(__floats2half2_rn(q2.x, q2.y)), h2u(__floats2half2_rn(q2.z, q2.w)));
                s3 = make_uint2(h2u(__floats2half2_rn(q3.x, q3.y)), h2u(__floats2half2_rn(q3.z, q3.w)));
            }
            const int bo = 8 + 8 * vc + j * PITCHB;
            *(uint2*)(qsm + 0 * HALO * PITCHB + bo) = s0;
            *(uint2*)(qsm + 1 * HALO * PITCHB + bo) = s1;
            *(uint2*)(qsm + 2 * HALO * PITCHB + bo) = s2v;
            *(uint2*)(qsm + 3 * HALO * PITCHB + bo) = s3;
        }
        __syncthreads();

        // ---- Phase 2: separable sobel in packed half2 ----
        {
            const __half2 TWOH = __half2half2(__float2half(2.0f));
            const __half2 ZERO = __half2half2(__float2half(0.0f));
            const unsigned char* rp = rbase;

            __half2 pu[2], pv[2], cu[2], cv[2];

#define ROW_UV(RP, U, V)                                                  \
    {                                                                     \
        const unsigned eL = *(const unsigned*)((RP) + 4 + off2);          \
        const uint2    M  = *(const uint2*)((RP) + 8 + off2);             \
        const unsigned eR = *(const unsigned*)((RP) + 16 + off2);         \
        const __half2 S0 = u2h(__byte_perm(eL, M.x, 0x5432));             \
        const __half2 S1 = u2h(__byte_perm(M.x, M.y, 0x5432));            \
        const __half2 S2 = u2h(__byte_perm(M.y, eR, 0x5432));             \
        U[0] = __hfma2(u2h(M.x), TWOH, __hadd2(S0, S1));                  \
        U[1] = __hfma2(u2h(M.y), TWOH, __hadd2(S1, S2));                  \
        V[0] = __hsub2(S1, S0);                                           \
        V[1] = __hsub2(S2, S1);                                           \
    }

            ROW_UV(rp, pu, pv); rp += PITCHB;
            ROW_UV(rp, cu, cv); rp += PITCHB;

#pragma unroll
            for (int half_blk = 0; half_blk < 2; half_blk++) {
                __half2 axh = ZERO, ayh = ZERO;
#pragma unroll
                for (int k = 0; k < 4; k++) {
                    __half2 nu[2], nv[2];
                    ROW_UV(rp, nu, nv); rp += PITCHB;
#pragma unroll
                    for (int i = 0; i < 2; i++) {
                        const __half2 gx = __hfma2(cv[i], TWOH, __hadd2(pv[i], nv[i]));
                        const __half2 gy = __hsub2(nu[i], pu[i]);
                        axh = __hfma2(gx, gx, axh);
                        ayh = __hfma2(gy, gy, ayh);
                        pu[i] = cu[i]; pv[i] = cv[i];
                        cu[i] = nu[i]; cv[i] = nv[i];
                    }
                }
                const float2 fx = __half22float2(axh);
                const float2 fy = __half22float2(ayh);
                axs += fx.x + fx.y;
                ays += fy.x + fy.y;
            }
#undef ROW_UV
        }

        if (t + 1 < t0 + ntl) __syncthreads();   // q overwrite hazard
    }

    float acc = axs + 2.f * ays;

    // ---- block reduction -> per-block partial ----
#pragma unroll
    for (int o = 16; o > 0; o >>= 1)
        acc += __shfl_down_sync(0xffffffffu, acc, o);
    if ((tid & 31) == 0) warpsum[tid >> 5] = acc;
    __syncthreads();

    if (tid == 0) {
        float sm = 0.f;
#pragma unroll
        for (int i = 0; i < NWARP; i++) sm += warpsum[i];
        g_partial[blockIdx.x] = sm;
        __threadfence();
        is_last = (atomicAdd(&g_count, 1) == NPBLK - 1);
    }
    __syncthreads();

    // ---- last block: final reduction + output + counter reset ----
    if (is_last) {
        double sd = 0.0;
        for (int i = tid; i < NPBLK; i += NTHREADS) sd += (double)g_partial[i];
#pragma unroll
        for (int o = 16; o > 0; o >>= 1)
            sd += __shfl_down_sync(0xffffffffu, sd, o);
        if ((tid & 31) == 0) dwarpsum[tid >> 5] = sd;
        __syncthreads();
        if (tid == 0) {
            double tot = 0.0;
#pragma unroll
            for (int i = 0; i < NWARP; i++) tot += dwarpsum[i];
            const double per_tensor = (double)BB * (DD + 2) * (HH + 2) * (WW + 2);
            out[0] = (float)(tot / per_tensor / (double)CC);
            g_count = 0;
        }
    }
}

extern "C" void kernel_launch(void* const* d_in, const int* in_sizes, int n_in,
                              void* d_out, int out_size)
{
    const float* pred   = (const float*)d_in[0];
    const int*   target = (const int*)d_in[1];
    float*       out    = (float*)d_out;

    bl_main_kernel<<<NPBLK, NTHREADS>>>(pred, target, out);
}